// round 11
// baseline (speedup 1.0000x reference)
#include <cuda_runtime.h>
#include <cstdint>

// LocalPatternExtractor: reference forward output is identically zero.
//
// Proof (forward values; stop_gradient is identity in the forward pass):
//   quantize_pot_ste clips round(mem*128) to [-128,127] -> mem <= 127/128 =
//   0.9921875 < THRESHOLD (1.0) -> spike (mem >= 1.0) is always false ->
//   acc = 0 over all 4 timesteps -> out = zeros, reg_loss = 0.
//   (Confirmed rel_err = 0.0 across rounds 2-10.)
//
// Established experimentally (82 MB zero-fill):
//   - STG.128 ~4.0 TB/s; STG.256 ~5.8 TB/s; TMA bulk ~5.8 TB/s;
//     concurrent STG.256+TMA on disjoint halves: STILL ~5.8 TB/s.
//     => shared chip-level L2 write-acceptance cap (~3200 B/cyc, half the
//     read-path LTS cap); ncu "L2=48%" = saturated write port.
//   - driver memset: 14.8us end-to-end (best) — same bandwidth class, but
//     cheaper graph-node replay than a user kernel node.
// Remaining lever: our memset size (81,920,004 B) is only 4B-aligned; an
// odd-size fill can force the driver onto a narrower fill kernel. Split into
// a 16B-multiple body + 4B tail so the body takes the widest path.

extern "C" void kernel_launch(void* const* d_in, const int* in_sizes, int n_in,
                              void* d_out, int out_size) {
    (void)d_in; (void)in_sizes; (void)n_in;

    size_t bytes = (size_t)out_size * sizeof(float);   // 81,920,004
    size_t body = bytes & ~(size_t)15;                 // 81,920,000 (16B mult)

    // Wide-path body fill.
    cudaMemsetAsync(d_out, 0, body, 0);
    // 4-byte tail (same stream; sequential, negligible).
    if (bytes != body) {
        cudaMemsetAsync((char*)d_out + body, 0, bytes - body, 0);
    }
}

// round 13
// speedup vs baseline: 1.0809x; 1.0809x over previous
#include <cuda_runtime.h>
#include <cstdint>

// LocalPatternExtractor: reference forward output is identically zero.
//   quantize clips mem <= 127/128 < THRESHOLD=1.0 -> spike always 0 ->
//   out = zeros(16,256,5000), reg_loss = 0. (rel_err = 0.0, rounds 2-11.)
//
// Established:
//   - All SM store paths (STG.128/256, TMA bulk, combined) cap at ~5.8 TB/s
//     (shared SM->L2 write-acceptance port).
//   - Graph memset node: ~12.2us device (~6.7 TB/s) + ~2.6us node overhead
//     -> 14.8us; exceeds the SM cap -> likely a distinct fill path (CE or
//     privileged fill kernel).
//   - Each extra graph node costs ~2.5-2.7us replay overhead.
// This round: memset node || STG.256 kernel node on DISJOINT halves. If the
// two write paths are independent they add (~12.5 TB/s aggregate).

static cudaStream_t g_s1 = nullptr;
static cudaEvent_t g_ev_fork = nullptr;
static cudaEvent_t g_ev_join = nullptr;

namespace {
struct StreamInit {
    StreamInit() {
        cudaStreamCreateWithFlags(&g_s1, cudaStreamNonBlocking);
        cudaEventCreateWithFlags(&g_ev_fork, cudaEventDisableTiming);
        cudaEventCreateWithFlags(&g_ev_join, cudaEventDisableTiming);
    }
};
StreamInit g_stream_init;
}  // namespace

__global__ void __launch_bounds__(256)
zero_fill_256(double* __restrict__ out, size_t n_chunks,
              float* __restrict__ tail, int n_tail) {
    const size_t stride = (size_t)gridDim.x * blockDim.x;
    size_t i = (size_t)blockIdx.x * blockDim.x + threadIdx.x;
    const double z = 0.0;
    for (; i < n_chunks; i += stride) {
        double* p = out + i * 4;
        asm volatile("st.global.v4.f64 [%0], {%1, %1, %1, %1};"
                     :: "l"(p), "d"(z) : "memory");
    }
    size_t t = (size_t)blockIdx.x * blockDim.x + threadIdx.x;
    if (t < (size_t)n_tail) {
        tail[t] = 0.f;
    }
}

extern "C" void kernel_launch(void* const* d_in, const int* in_sizes, int n_in,
                              void* d_out, int out_size) {
    (void)d_in; (void)in_sizes; (void)n_in;

    char* p = (char*)d_out;
    size_t bytes = (size_t)out_size * sizeof(float);     // 81,920,004
    // Split ~53% to the memset path (it's the faster one), 32B-aligned.
    size_t ms_bytes = ((size_t)(bytes * 0.53)) & ~(size_t)31;
    size_t rest = bytes - ms_bytes;                      // kernel region
    size_t n_chunks = rest / 32;                         // 32B STG.256 chunks
    size_t covered = ms_bytes + n_chunks * 32;
    int n_tail = (int)((bytes - covered) / 4);           // leftover floats
    float* tail_ptr = (float*)(p + covered);

    // Fork side stream off the capture stream.
    cudaEventRecord(g_ev_fork, 0);
    cudaStreamWaitEvent(g_s1, g_ev_fork, 0);

    // Parallel branches: memset path on stream 0, SM store path on s1.
    cudaMemsetAsync(p, 0, ms_bytes, 0);
    zero_fill_256<<<1184, 256, 0, g_s1>>>((double*)(p + ms_bytes), n_chunks,
                                          tail_ptr, n_tail);

    // Join.
    cudaEventRecord(g_ev_join, g_s1);
    cudaStreamWaitEvent(0, g_ev_join, 0);
}